// round 4
// baseline (speedup 1.0000x reference)
#include <cuda_runtime.h>
#include <math.h>

#define BATCH 2
#define NP    4096
#define HH    128
#define WW    128
#define KK    8
#define RAD   0.05f
#define RAD2  (RAD * RAD)
#define TILE  16
#define TX    (WW / TILE)   // 8
#define TYN   (HH / TILE)   // 8
#define NTILES (TX * TYN)   // 64
#define SN    512            // bitonic sort capacity (power of 2 >= max tile count)

#define ZINF 3.0e38f

// Global scratch (no cudaMalloc allowed)
__device__ int    g_cnt[BATCH * NTILES];        // zero-init at load; raster re-zeroes
__device__ float4 g_list[BATCH * NTILES * NP];

// ---------------------------------------------------------------------------
// Kernel A: world->view->NDC transform + scatter float4 record into tiles
// ---------------------------------------------------------------------------
__global__ void transform_bin_kernel(const float* __restrict__ pts,
                                     const float* __restrict__ Rm,
                                     const float* __restrict__ Tv,
                                     const float* __restrict__ Fc) {
    int t = blockIdx.x * blockDim.x + threadIdx.x;
    if (t >= BATCH * NP) return;
    int b = t / NP;
    int p = t - b * NP;

    float p0 = pts[t * 3 + 0];
    float p1 = pts[t * 3 + 1];
    float p2 = pts[t * 3 + 2];
    const float* Rb = Rm + b * 9;
    const float* Tb = Tv + b * 3;

    // row-vector convention: v[j] = sum_i p[i] * R[i][j] + T[j]
    float xv = p0 * Rb[0] + p1 * Rb[3] + p2 * Rb[6] + Tb[0];
    float yv = p0 * Rb[1] + p1 * Rb[4] + p2 * Rb[7] + Tb[1];
    float zv = p0 * Rb[2] + p1 * Rb[5] + p2 * Rb[8] + Tb[2];

    float f = Fc[b];
    float x = f * xv / zv;   // IEEE div, matches reference
    float y = f * yv / zv;

    if (!(zv > 0.0f)) return;

    // pixel ix covered iff |gx(ix) - x| < r, gx(ix) = 1 - (ix+0.5)/64
    float lox = 64.0f * (1.0f - x - RAD) - 0.5f;
    float hix = 64.0f * (1.0f - x + RAD) - 0.5f;
    float loy = 64.0f * (1.0f - y - RAD) - 0.5f;
    float hiy = 64.0f * (1.0f - y + RAD) - 0.5f;

    if (!(hix >= 0.0f) || !(lox <= (float)(WW - 1))) return;
    if (!(hiy >= 0.0f) || !(loy <= (float)(HH - 1))) return;

    int ix0 = max(0, (int)floorf(fmaxf(lox, 0.0f)));
    int ix1 = min(WW - 1, (int)ceilf(fminf(hix, (float)(WW - 1))));
    int iy0 = max(0, (int)floorf(fmaxf(loy, 0.0f)));
    int iy1 = min(HH - 1, (int)ceilf(fminf(hiy, (float)(HH - 1))));
    if (ix0 > ix1 || iy0 > iy1) return;

    int tx0 = ix0 >> 4, tx1 = ix1 >> 4;
    int ty0 = iy0 >> 4, ty1 = iy1 >> 4;

    float4 rec = make_float4(x, y, zv, (float)p);
    for (int ty = ty0; ty <= ty1; ty++) {
        for (int tx = tx0; tx <= tx1; tx++) {
            int tile = b * NTILES + ty * TX + tx;
            int pos = atomicAdd(&g_cnt[tile], 1);
            g_list[tile * NP + pos] = rec;
        }
    }
}

// ---------------------------------------------------------------------------
// Kernel B: per-tile raster. 256 threads = 1/pixel.
// Sort candidates by z (bitonic, smem), then append-only scan w/ early exit.
// ---------------------------------------------------------------------------
__global__ void __launch_bounds__(256) raster_kernel(float* __restrict__ out) {
    __shared__ float4 s[SN];      // 8 KB
    __shared__ int s_n;

    const int tx = blockIdx.x, ty = blockIdx.y, b = blockIdx.z;
    const int tid = threadIdx.x;
    const int tile = b * NTILES + ty * TX + tx;

    if (tid == 0) {
        s_n = g_cnt[tile];
        g_cnt[tile] = 0;          // reset for next graph replay (own counter)
    }
    __syncthreads();
    const int n = s_n;
    const float4* __restrict__ list = g_list + tile * NP;

    const int lx = tid & 15, ly = tid >> 4;
    const int px = tx * TILE + lx;
    const int py = ty * TILE + ly;
    const float gx = 1.0f - (px + 0.5f) * (1.0f / 64.0f);
    const float gy = 1.0f - (py + 0.5f) * (1.0f / 64.0f);

    float zb[KK], db[KK], ib[KK];
#pragma unroll
    for (int k = 0; k < KK; k++) { zb[k] = -1.0f; db[k] = -1.0f; ib[k] = -1.0f; }
    int cnt = 0;

    if (n <= SN) {
        // ---- fast path: load, pad, bitonic sort ascending by z ----
#pragma unroll
        for (int i = tid; i < SN; i += 256)
            s[i] = (i < n) ? list[i] : make_float4(0.f, 0.f, ZINF, -1.f);

        for (int k = 2; k <= SN; k <<= 1) {
            for (int j = k >> 1; j > 0; j >>= 1) {
                __syncthreads();
#pragma unroll
                for (int i = tid; i < SN; i += 256) {
                    int ixj = i ^ j;
                    if (ixj > i) {
                        float4 a = s[i];
                        float4 c = s[ixj];
                        bool up = ((i & k) == 0);
                        if ((a.z > c.z) == up) { s[i] = c; s[ixj] = a; }
                    }
                }
            }
        }
        __syncthreads();

        // ---- append-only scan in ascending z; warp-wide early exit ----
        for (int j = 0; j < n; j++) {
            float4 c = s[j];
            float dx = gx - c.x;
            float dy = gy - c.y;
            float d2 = fmaf(dx, dx, dy * dy);
            if (d2 < RAD2 && cnt < KK) {
#pragma unroll
                for (int k = 0; k < KK; k++) {
                    if (cnt == k) { zb[k] = c.z; db[k] = d2; ib[k] = c.w; }
                }
                cnt++;
            }
            if ((j & 7) == 7 && __all_sync(0xffffffffu, cnt == KK)) break;
        }
    } else {
        // ---- safety fallback (never taken with this data): insertion scan ----
        float zw[KK];
#pragma unroll
        for (int k = 0; k < KK; k++) zw[k] = ZINF;
        for (int base = 0; base < n; base += SN) {
            int m = min(SN, n - base);
            __syncthreads();
            for (int i = tid; i < m; i += 256) s[i] = list[base + i];
            __syncthreads();
            for (int j = 0; j < m; j++) {
                float4 c = s[j];
                float dx = gx - c.x;
                float dy = gy - c.y;
                float d2 = fmaf(dx, dx, dy * dy);
                if (d2 < RAD2 && c.z < zw[KK - 1]) {
                    float zi = c.z, di = d2, ii = c.w;
#pragma unroll
                    for (int k = 0; k < KK; k++) {
                        if (zi < zw[k]) {
                            float t;
                            t = zw[k]; zw[k] = zi; zi = t;
                            t = db[k]; db[k] = di; di = t;
                            t = ib[k]; ib[k] = ii; ii = t;
                        }
                    }
                }
            }
        }
#pragma unroll
        for (int k = 0; k < KK; k++) {
            bool v = zw[k] < ZINF;
            zb[k] = v ? zw[k] : -1.0f;
            if (!v) { db[k] = -1.0f; ib[k] = -1.0f; }
        }
        cnt = KK;  // zb/db/ib already hold final (-1-filled) values
    }

    // ---- Output: [idx | zbuf | dists], each [B,H,W,K] ----
    const int N = BATCH * HH * WW * KK;
    const int obase = ((b * HH + py) * WW + px) * KK;
#pragma unroll
    for (int k = 0; k < KK; k++) {
        out[obase + k]         = ib[k];
        out[N + obase + k]     = zb[k];
        out[2 * N + obase + k] = db[k];
    }
}

// ---------------------------------------------------------------------------
extern "C" void kernel_launch(void* const* d_in, const int* in_sizes, int n_in,
                              void* d_out, int out_size) {
    const float* pts = (const float*)d_in[0];
    const float* Rm  = (const float*)d_in[1];
    const float* Tv  = (const float*)d_in[2];
    const float* Fc  = (const float*)d_in[3];
    float* out = (float*)d_out;

    transform_bin_kernel<<<(BATCH * NP + 255) / 256, 256>>>(pts, Rm, Tv, Fc);
    raster_kernel<<<dim3(TX, TYN, BATCH), 256>>>(out);
}

// round 5
// speedup vs baseline: 1.5271x; 1.5271x over previous
#include <cuda_runtime.h>
#include <math.h>

#define BATCH 2
#define NP    4096
#define HH    128
#define WW    128
#define KK    8
#define RAD   0.05f
#define RAD2  (RAD * RAD)
#define TILE  8
#define TX    (WW / TILE)   // 16
#define TYN   (HH / TILE)   // 16
#define NTILES (TX * TYN)   // 256
#define NPIX  (TILE * TILE) // 64 threads per CTA
#define CHUNK 512

#define ZINF 3.0e38f

// Global scratch (no cudaMalloc allowed)
__device__ int    g_cnt[BATCH * NTILES];          // zero-init at load; raster re-zeroes
__device__ float4 g_list[BATCH * NTILES * NP];    // 32 MB, un-overflowable

// ---------------------------------------------------------------------------
// Kernel A: world->view->NDC transform + scatter float4 record into tiles
// ---------------------------------------------------------------------------
__global__ void transform_bin_kernel(const float* __restrict__ pts,
                                     const float* __restrict__ Rm,
                                     const float* __restrict__ Tv,
                                     const float* __restrict__ Fc) {
    int t = blockIdx.x * blockDim.x + threadIdx.x;
    if (t >= BATCH * NP) return;
    int b = t / NP;
    int p = t - b * NP;

    float p0 = pts[t * 3 + 0];
    float p1 = pts[t * 3 + 1];
    float p2 = pts[t * 3 + 2];
    const float* Rb = Rm + b * 9;
    const float* Tb = Tv + b * 3;

    // row-vector convention: v[j] = sum_i p[i] * R[i][j] + T[j]
    float xv = p0 * Rb[0] + p1 * Rb[3] + p2 * Rb[6] + Tb[0];
    float yv = p0 * Rb[1] + p1 * Rb[4] + p2 * Rb[7] + Tb[1];
    float zv = p0 * Rb[2] + p1 * Rb[5] + p2 * Rb[8] + Tb[2];

    float f = Fc[b];
    float x = f * xv / zv;   // IEEE div, matches reference
    float y = f * yv / zv;

    if (!(zv > 0.0f)) return;

    // pixel ix covered iff |gx(ix) - x| < r, gx(ix) = 1 - (ix+0.5)/64
    float lox = 64.0f * (1.0f - x - RAD) - 0.5f;
    float hix = 64.0f * (1.0f - x + RAD) - 0.5f;
    float loy = 64.0f * (1.0f - y - RAD) - 0.5f;
    float hiy = 64.0f * (1.0f - y + RAD) - 0.5f;

    if (!(hix >= 0.0f) || !(lox <= (float)(WW - 1))) return;
    if (!(hiy >= 0.0f) || !(loy <= (float)(HH - 1))) return;

    int ix0 = max(0, (int)floorf(fmaxf(lox, 0.0f)));
    int ix1 = min(WW - 1, (int)ceilf(fminf(hix, (float)(WW - 1))));
    int iy0 = max(0, (int)floorf(fmaxf(loy, 0.0f)));
    int iy1 = min(HH - 1, (int)ceilf(fminf(hiy, (float)(HH - 1))));
    if (ix0 > ix1 || iy0 > iy1) return;

    int tx0 = ix0 / TILE, tx1 = ix1 / TILE;
    int ty0 = iy0 / TILE, ty1 = iy1 / TILE;

    float4 rec = make_float4(x, y, zv, (float)p);
    for (int ty = ty0; ty <= ty1; ty++) {
        for (int tx = tx0; tx <= tx1; tx++) {
            int tile = b * NTILES + ty * TX + tx;
            int pos = atomicAdd(&g_cnt[tile], 1);
            g_list[tile * NP + pos] = rec;
        }
    }
}

// ---------------------------------------------------------------------------
// Kernel B: per-tile raster. 8x8 tile, 64 threads = 1/pixel.
// Register-resident sorted top-8 insertion scan. Resets own counter.
// ---------------------------------------------------------------------------
__global__ void __launch_bounds__(NPIX) raster_kernel(float* __restrict__ out) {
    __shared__ float4 sc[CHUNK];   // 8 KB
    __shared__ int s_n;

    const int tx = blockIdx.x, ty = blockIdx.y, b = blockIdx.z;
    const int tid = threadIdx.x;
    const int tile = b * NTILES + ty * TX + tx;

    if (tid == 0) {
        s_n = g_cnt[tile];
        g_cnt[tile] = 0;           // reset for next graph replay (own counter only)
    }
    __syncthreads();
    const int n = s_n;
    const float4* __restrict__ list = g_list + tile * NP;

    const int lx = tid & (TILE - 1), ly = tid / TILE;
    const int px = tx * TILE + lx;
    const int py = ty * TILE + ly;
    const float gx = 1.0f - (px + 0.5f) * (1.0f / 64.0f);
    const float gy = 1.0f - (py + 0.5f) * (1.0f / 64.0f);

    float zb[KK], db[KK], ib[KK];
#pragma unroll
    for (int k = 0; k < KK; k++) { zb[k] = ZINF; db[k] = -1.0f; ib[k] = -1.0f; }

    for (int base = 0; base < n; base += CHUNK) {
        int m = min(CHUNK, n - base);
        __syncthreads();
        for (int i = tid; i < m; i += NPIX)
            sc[i] = list[base + i];          // coalesced 16B loads
        __syncthreads();

#pragma unroll 2
        for (int j = 0; j < m; j++) {
            float4 c = sc[j];                // LDS.128 broadcast
            float dx = gx - c.x;
            float dy = gy - c.y;
            float d2 = fmaf(dx, dx, dy * dy);
            if (d2 < RAD2 && c.z < zb[KK - 1]) {
                float zi = c.z, di = d2, ii = c.w;
#pragma unroll
                for (int k = 0; k < KK; k++) {
                    if (zi < zb[k]) {
                        float t;
                        t = zb[k]; zb[k] = zi; zi = t;
                        t = db[k]; db[k] = di; di = t;
                        t = ib[k]; ib[k] = ii; ii = t;
                    }
                }
            }
        }
    }

    // ---- Output: [idx | zbuf | dists], each [B,H,W,K] ----
    const int N = BATCH * HH * WW * KK;
    const int obase = ((b * HH + py) * WW + px) * KK;
#pragma unroll
    for (int k = 0; k < KK; k++) {
        bool v = zb[k] < ZINF;
        out[obase + k]         = v ? ib[k] : -1.0f;
        out[N + obase + k]     = v ? zb[k] : -1.0f;
        out[2 * N + obase + k] = v ? db[k] : -1.0f;
    }
}

// ---------------------------------------------------------------------------
extern "C" void kernel_launch(void* const* d_in, const int* in_sizes, int n_in,
                              void* d_out, int out_size) {
    const float* pts = (const float*)d_in[0];
    const float* Rm  = (const float*)d_in[1];
    const float* Tv  = (const float*)d_in[2];
    const float* Fc  = (const float*)d_in[3];
    float* out = (float*)d_out;

    transform_bin_kernel<<<(BATCH * NP + 255) / 256, 256>>>(pts, Rm, Tv, Fc);
    raster_kernel<<<dim3(TX, TYN, BATCH), NPIX>>>(out);
}